// round 6
// baseline (speedup 1.0000x reference)
#include <cuda_runtime.h>
#include <cstddef>

// Problem constants
#define BB   16
#define SS   1024
#define DM   256
#define BSN  (BB*SS)             // 16384
#define OUT_ELEMS   (BSN*DM)     // 4,194,304
#define ATTN_ELEMS  (BB*8*SS*SS) // 134,217,728

typedef unsigned long long u64;

__device__ __forceinline__ float to_tf32(float x) {
    float r; asm("cvt.rna.tf32.f32 %0, %1;" : "=f"(r) : "f"(x)); return r;
}
__device__ __forceinline__ void mma_tf32(float* d, float a0, float a1, float a2, float a3,
                                         float b0, float b1) {
    asm("mma.sync.aligned.m16n8k8.row.col.f32.tf32.tf32.f32 "
        "{%0,%1,%2,%3}, {%4,%5,%6,%7}, {%8,%9}, {%0,%1,%2,%3};"
        : "+f"(d[0]), "+f"(d[1]), "+f"(d[2]), "+f"(d[3])
        : "r"(__float_as_uint(a0)), "r"(__float_as_uint(a1)),
          "r"(__float_as_uint(a2)), "r"(__float_as_uint(a3)),
          "r"(__float_as_uint(b0)), "r"(__float_as_uint(b1)));
}

// ---------------- scratch (static device memory; no allocation) -------------
__device__ float g_Wq[256*256], g_Wk[256*256], g_Wv[256*256];
__device__ float g_bq[256],     g_bk[256],     g_bv[256];
__device__ float g_Q [BSN*DM];
__device__ float g_K [BSN*DM];
__device__ float g_V [BSN*DM];
__device__ float g_KT[BSN*DM];            // (b, n, s)
__device__ float g_O [BSN*DM];            // concat(o_dist, o_adj)
__device__ float g_Dsm[(size_t)BB*SS*SS]; // softmax(dist + neg)

// ---------------- fused weight packing ---------------------------------------
__global__ void pack3_kernel(
    const float* __restrict__ Wqd, const float* __restrict__ Wqa,
    const float* __restrict__ bqd, const float* __restrict__ bqa,
    const float* __restrict__ Wkd, const float* __restrict__ Wka,
    const float* __restrict__ bkd, const float* __restrict__ bka,
    const float* __restrict__ Wvd, const float* __restrict__ Wva,
    const float* __restrict__ bvd, const float* __restrict__ bva,
    float* __restrict__ Wq, float* __restrict__ bq,
    float* __restrict__ Wk, float* __restrict__ bk,
    float* __restrict__ Wv, float* __restrict__ bv) {
    int k = blockIdx.x, n = threadIdx.x, w = blockIdx.y;
    const float* Wd = (w == 0) ? Wqd : (w == 1) ? Wkd : Wvd;
    const float* Wa = (w == 0) ? Wqa : (w == 1) ? Wka : Wva;
    const float* bd = (w == 0) ? bqd : (w == 1) ? bkd : bvd;
    const float* ba = (w == 0) ? bqa : (w == 1) ? bka : bva;
    float* W    = (w == 0) ? Wq : (w == 1) ? Wk : Wv;
    float* bias = (w == 0) ? bq : (w == 1) ? bk : bv;
    W[k*256 + n] = (n < 128) ? Wd[k*128 + n] : Wa[k*128 + (n-128)];
    if (k == 0) bias[n] = (n < 128) ? bd[n] : ba[n-128];
}

// ---------------- tf32-split GEMM: C = A @ W + bias (near-fp32 precision) ---
// 128x128 CTA tile, 8 warps (2x4), warp tile 64x32, m16n8k8.
// 3-term split: C ~= Ahi*Whi + Ahi*Wlo + Alo*Whi.
// smem: Ahi/Alo 128x36, Whi/Wlo 32x132. 17664 fl = 70,656 B.
__global__ __launch_bounds__(256)
void gemmT_kernel(const float* __restrict__ A, const float* __restrict__ W,
                  const float* __restrict__ bias, float* __restrict__ C) {
    extern __shared__ float smg[];
    float* Ahi = smg;            // 4608
    float* Alo = smg + 4608;     // 4608
    float* Whi = smg + 9216;     // 4224
    float* Wlo = smg + 13440;    // 4224

    const int t    = threadIdx.x;
    const int lane = t & 31, warp = t >> 5;
    const int g = lane >> 2, c = lane & 3;
    const int mw = (warp & 1) * 64, nw = (warp >> 1) * 32;
    const int m0 = blockIdx.x * 128, n0 = blockIdx.y * 128;

    float acc[4][4][4];
    #pragma unroll
    for (int mt = 0; mt < 4; ++mt)
        #pragma unroll
        for (int nt = 0; nt < 4; ++nt)
            #pragma unroll
            for (int j = 0; j < 4; ++j) acc[mt][nt][j] = 0.f;

    for (int k0 = 0; k0 < 256; k0 += 32) {
        __syncthreads();
        #pragma unroll
        for (int u = 0; u < 4; ++u) {      // A tile 128x32
            int fi = t + u*256;
            int row = fi >> 3, c4 = fi & 7;
            float4 v = *(const float4*)(A + (size_t)(m0+row)*256 + k0 + c4*4);
            float4 h, l;
            h.x = to_tf32(v.x); l.x = to_tf32(v.x - h.x);
            h.y = to_tf32(v.y); l.y = to_tf32(v.y - h.y);
            h.z = to_tf32(v.z); l.z = to_tf32(v.z - h.z);
            h.w = to_tf32(v.w); l.w = to_tf32(v.w - h.w);
            *(float4*)(&Ahi[row*36 + c4*4]) = h;
            *(float4*)(&Alo[row*36 + c4*4]) = l;
        }
        #pragma unroll
        for (int u = 0; u < 4; ++u) {      // W tile 32x128
            int fi = t + u*256;
            int kr = fi >> 5, n4 = fi & 31;
            float4 v = *(const float4*)(W + (size_t)(k0+kr)*256 + n0 + n4*4);
            float4 h, l;
            h.x = to_tf32(v.x); l.x = to_tf32(v.x - h.x);
            h.y = to_tf32(v.y); l.y = to_tf32(v.y - h.y);
            h.z = to_tf32(v.z); l.z = to_tf32(v.z - h.z);
            h.w = to_tf32(v.w); l.w = to_tf32(v.w - h.w);
            *(float4*)(&Whi[kr*132 + n4*4]) = h;
            *(float4*)(&Wlo[kr*132 + n4*4]) = l;
        }
        __syncthreads();
        #pragma unroll
        for (int ks = 0; ks < 4; ++ks) {
            float ah[4][4], al[4][4];
            #pragma unroll
            for (int mt = 0; mt < 4; ++mt) {
                int r = mw + mt*16 + g;
                ah[mt][0] = Ahi[r*36 + ks*8 + c];
                ah[mt][1] = Ahi[(r+8)*36 + ks*8 + c];
                ah[mt][2] = Ahi[r*36 + ks*8 + c + 4];
                ah[mt][3] = Ahi[(r+8)*36 + ks*8 + c + 4];
                al[mt][0] = Alo[r*36 + ks*8 + c];
                al[mt][1] = Alo[(r+8)*36 + ks*8 + c];
                al[mt][2] = Alo[r*36 + ks*8 + c + 4];
                al[mt][3] = Alo[(r+8)*36 + ks*8 + c + 4];
            }
            #pragma unroll
            for (int nt = 0; nt < 4; ++nt) {
                int n = nw + nt*8 + g;
                float bh0 = Whi[(ks*8 + c)*132 + n];
                float bh1 = Whi[(ks*8 + c + 4)*132 + n];
                float bl0 = Wlo[(ks*8 + c)*132 + n];
                float bl1 = Wlo[(ks*8 + c + 4)*132 + n];
                #pragma unroll
                for (int mt = 0; mt < 4; ++mt) {
                    mma_tf32(acc[mt][nt], ah[mt][0], ah[mt][1], ah[mt][2], ah[mt][3], bh0, bh1);
                    mma_tf32(acc[mt][nt], ah[mt][0], ah[mt][1], ah[mt][2], ah[mt][3], bl0, bl1);
                    mma_tf32(acc[mt][nt], al[mt][0], al[mt][1], al[mt][2], al[mt][3], bh0, bh1);
                }
            }
        }
    }

    // epilogue: add bias, write
    #pragma unroll
    for (int nt = 0; nt < 4; ++nt) {
        int col = n0 + nw + nt*8 + c*2;
        float2 bb = *(const float2*)(bias + col);
        #pragma unroll
        for (int mt = 0; mt < 4; ++mt) {
            int r = m0 + mw + mt*16 + g;
            float2 o;
            o.x = acc[mt][nt][0] + bb.x; o.y = acc[mt][nt][1] + bb.y;
            *(float2*)(C + (size_t)r*256 + col) = o;
            o.x = acc[mt][nt][2] + bb.x; o.y = acc[mt][nt][3] + bb.y;
            *(float2*)(C + (size_t)(r+8)*256 + col) = o;
        }
    }
}

// ---------------- prep: dist softmax + K transpose (fused launch) -----------
__global__ __launch_bounds__(256)
void prep_kernel(const float* __restrict__ dist, const float* __restrict__ mask,
                 const float* __restrict__ Kp, float* __restrict__ Dsm,
                 float* __restrict__ KT) {
    __shared__ float tile[32][33];
    __shared__ float ws[8];
    const int blk = blockIdx.x;
    const int t = threadIdx.x;
    if (blk < 16384) {
        const int b = blk >> 10, q = blk & 1023;
        const float* drow = dist + ((size_t)b*SS + q)*SS;
        const float* mrow = mask + (size_t)b*SS;
        float e[4], s = 0.f;
        #pragma unroll
        for (int u = 0; u < 4; ++u) {
            int k = t + u*256;
            e[u] = __expf(drow[k] + mrow[k] * -1e9f);
            s += e[u];
        }
        #pragma unroll
        for (int off = 16; off; off >>= 1) s += __shfl_xor_sync(0xffffffffu, s, off);
        if ((t & 31) == 0) ws[t >> 5] = s;
        __syncthreads();
        float tot = 0.f;
        #pragma unroll
        for (int w = 0; w < 8; ++w) tot += ws[w];
        const float inv = 1.f / tot;
        float* orow = Dsm + ((size_t)b*SS + q)*SS;
        #pragma unroll
        for (int u = 0; u < 4; ++u) orow[t + u*256] = e[u] * inv;
    } else {
        const int r  = (blk - 16384) & 255;
        const int b  = (blk - 16384) >> 8;
        const int n0 = (r & 7) * 32;
        const int s0 = (r >> 3) * 32;
        const int tx = t & 31, ty = t >> 5;
        const float* src = Kp + ((size_t)b*SS + s0)*256 + n0;
        #pragma unroll
        for (int i = 0; i < 32; i += 8)
            tile[ty+i][tx] = src[(size_t)(ty+i)*256 + tx];
        __syncthreads();
        float* dst = KT + ((size_t)b*256 + n0)*SS + s0;
        #pragma unroll
        for (int i = 0; i < 32; i += 8)
            dst[(size_t)(ty+i)*SS + tx] = tile[tx][ty+i];
    }
}

// ---------------- fused attention: 64 queries/CTA, two-pass streaming -------
__global__ __launch_bounds__(256, 2)
void attn_kernel(const float* __restrict__ Q, const float* __restrict__ KT,
                 const float* __restrict__ V, const float* __restrict__ mask,
                 const float* __restrict__ extraD, const float* __restrict__ extraA,
                 float* __restrict__ attnw, float* __restrict__ Obuf) {
    extern __shared__ float sm[];
    float* q_sm = sm;              // 2304
    float* k_sm = sm + 2304;       // 4352 (stride 136)
    float* v_sm = sm + 6656;       // 5120 (stride 40)
    float* w_tl = sm + 11776;      // 8448 (stride 132; reused as partials 8x544)
    float* msk  = sm + 20224;      // 1024
    float* redu = sm + 21248;      // 192

    const int t    = threadIdx.x;
    const int lane = t & 31, warp = t >> 5;
    const int g = lane >> 2, c = lane & 3;
    const int mq = warp & 3, nh = warp >> 2;
    const int q0 = blockIdx.x * 64;
    const int hg = blockIdx.y;
    const int b  = blockIdx.z;
    const int coloff = hg * 32;
    const float* extra = (hg >= 4) ? extraA : extraD;

    #pragma unroll
    for (int u = 0; u < 8; ++u) {
        int i = t + u*256;
        int r = i >> 5, d = i & 31;
        q_sm[r*36 + d] = to_tf32(Q[(size_t)(b*SS + q0 + r)*256 + coloff + d]);
    }
    #pragma unroll
    for (int u = 0; u < 4; ++u)
        msk[t + u*256] = mask[b*SS + t + u*256] * -1e9f;

    const float* ktb   = KT + ((size_t)b*256 + coloff)*SS;
    const float* vbase = V + (size_t)b*SS*256 + coloff;
    const float scale = 0.17677669529663688f;

    const int rlo = mq*16 + g;
    const int rhi = rlo + 8;

    // =================== PASS 1: row sums ===================
    float s_lo = 0.f, s_hi = 0.f;
    for (int tile = 0; tile < 8; ++tile) {
        __syncthreads();
        #pragma unroll
        for (int u = 0; u < 4; ++u) {
            int fi = t + u*256;
            int kd = fi >> 5, c4 = fi & 31;
            float4 v = *(const float4*)(ktb + (size_t)kd*SS + tile*128 + c4*4);
            v.x = to_tf32(v.x); v.y = to_tf32(v.y);
            v.z = to_tf32(v.z); v.w = to_tf32(v.w);
            *(float4*)(&k_sm[kd*136 + c4*4]) = v;
        }
        __syncthreads();
        float acc[8][4];
        #pragma unroll
        for (int nt = 0; nt < 8; ++nt)
            #pragma unroll
            for (int j = 0; j < 4; ++j) acc[nt][j] = 0.f;
        #pragma unroll
        for (int ks = 0; ks < 4; ++ks) {
            float a0 = q_sm[rlo*36 + ks*8 + c];
            float a1 = q_sm[rhi*36 + ks*8 + c];
            float a2 = q_sm[rlo*36 + ks*8 + c + 4];
            float a3 = q_sm[rhi*36 + ks*8 + c + 4];
            #pragma unroll
            for (int nt = 0; nt < 8; ++nt) {
                int n0 = nh*64 + nt*8 + g;
                float b0 = k_sm[(ks*8 + c)*136 + n0];
                float b1 = k_sm[(ks*8 + c + 4)*136 + n0];
                mma_tf32(acc[nt], a0, a1, a2, a3, b0, b1);
            }
        }
        #pragma unroll
        for (int nt = 0; nt < 8; ++nt) {
            int key0 = tile*128 + nh*64 + nt*8 + c*2;
            float n0v = msk[key0], n1v = msk[key0+1];
            s_lo += __expf(fmaf(acc[nt][0], scale, n0v));
            s_lo += __expf(fmaf(acc[nt][1], scale, n1v));
            s_hi += __expf(fmaf(acc[nt][2], scale, n0v));
            s_hi += __expf(fmaf(acc[nt][3], scale, n1v));
        }
    }
    s_lo += __shfl_xor_sync(0xffffffffu, s_lo, 1);
    s_lo += __shfl_xor_sync(0xffffffffu, s_lo, 2);
    s_hi += __shfl_xor_sync(0xffffffffu, s_hi, 1);
    s_hi += __shfl_xor_sync(0xffffffffu, s_hi, 2);
    if (c == 0) {
        redu[nh*64 + rlo] = s_lo;
        redu[nh*64 + rhi] = s_hi;
    }
    __syncthreads();
    if (t < 64) redu[128 + t] = 1.f / (redu[t] + redu[64 + t]);

    const float* exlo = extra + ((size_t)b*SS + q0 + rlo)*SS;
    const float* exhi = extra + ((size_t)b*SS + q0 + rhi)*SS;
    float* wplo = attnw ? attnw + ((size_t)(b*8 + hg)*SS + q0 + rlo)*SS : (float*)0;
    float* wphi = attnw ? attnw + ((size_t)(b*8 + hg)*SS + q0 + rhi)*SS : (float*)0;

    // =================== PASS 2: weights + PV ===================
    float oc[4][4];
    #pragma unroll
    for (int nt = 0; nt < 4; ++nt)
        #pragma unroll
        for (int j = 0; j < 4; ++j) oc[nt][j] = 0.f;

    __syncthreads();
    const float inv_lo = redu[128 + rlo];
    const float inv_hi = redu[128 + rhi];

    for (int tile = 0; tile < 8; ++tile) {
        __syncthreads();
        #pragma unroll
        for (int u = 0; u < 4; ++u) {
            int fi = t + u*256;
            int kd = fi >> 5, c4 = fi & 31;
            float4 v = *(const float4*)(ktb + (size_t)kd*SS + tile*128 + c4*4);
            v.x = to_tf32(v.x); v.y = to_tf32(v.y);
            v.z = to_tf32(v.z); v.w = to_tf32(v.w);
            *(float4*)(&k_sm[kd*136 + c4*4]) = v;
        }
        #pragma unroll
        for (int u = 0; u < 4; ++u) {
            int fi = t + u*256;
            int kr = fi >> 3, q4 = fi & 7;
            float4 v = *(const float4*)(vbase + (size_t)(tile*128 + kr)*256 + q4*4);
            v.x = to_tf32(v.x); v.y = to_tf32(v.y);
            v.z = to_tf32(v.z); v.w = to_tf32(v.w);
            *(float4*)(&v_sm[kr*40 + q4*4]) = v;
        }
        __syncthreads();
        float acc[8][4];
        #pragma unroll
        for (int nt = 0; nt < 8; ++nt)
            #pragma unroll
            for (int j = 0; j < 4; ++j) acc[nt][j] = 0.f;
        #pragma unroll
        for (int ks = 0; ks < 4; ++ks) {
            float a0 = q_sm[rlo*36 + ks*8 + c];
            float a1 = q_sm[rhi*36 + ks*8 + c];
            float a2 = q_sm[rlo*36 + ks*8 + c + 4];
            float a3 = q_sm[rhi*36 + ks*8 + c + 4];
            #pragma unroll
            for (int nt = 0; nt < 8; ++nt) {
                int n0 = nh*64 + nt*8 + g;
                float b0 = k_sm[(ks*8 + c)*136 + n0];
                float b1 = k_sm[(ks*8 + c + 4)*136 + n0];
                mma_tf32(acc[nt], a0, a1, a2, a3, b0, b1);
            }
        }
        #pragma unroll
        for (int nt = 0; nt < 8; ++nt) {
            int lkey = nh*64 + nt*8 + c*2;
            int key0 = tile*128 + lkey;
            float n0v = msk[key0], n1v = msk[key0+1];
            float2 elo = *(const float2*)(exlo + key0);
            float2 ehi = *(const float2*)(exhi + key0);
            float w0 = __expf(fmaf(acc[nt][0], scale, n0v)) * inv_lo * elo.x;
            float w1 = __expf(fmaf(acc[nt][1], scale, n1v)) * inv_lo * elo.y;
            float w2 = __expf(fmaf(acc[nt][2], scale, n0v)) * inv_hi * ehi.x;
            float w3 = __expf(fmaf(acc[nt][3], scale, n1v)) * inv_hi * ehi.y;
            if (wplo) {
                float2 o; o.x = w0; o.y = w1; *(float2*)(wplo + key0) = o;
                o.x = w2; o.y = w3; *(float2*)(wphi + key0) = o;
            }
            float2 s;
            s.x = to_tf32(w0); s.y = to_tf32(w1);
            *(float2*)(&w_tl[rlo*132 + lkey]) = s;
            s.x = to_tf32(w2); s.y = to_tf32(w3);
            *(float2*)(&w_tl[rhi*132 + lkey]) = s;
        }
        __syncthreads();
        #pragma unroll
        for (int ks = 0; ks < 8; ++ks) {
            int kb = nh*64 + ks*8;
            float a0 = w_tl[rlo*132 + kb + c];
            float a1 = w_tl[rhi*132 + kb + c];
            float a2 = w_tl[rlo*132 + kb + c + 4];
            float a3 = w_tl[rhi*132 + kb + c + 4];
            #pragma unroll
            for (int nt = 0; nt < 4; ++nt) {
                float b0 = v_sm[(kb + c)*40 + nt*8 + g];
                float b1 = v_sm[(kb + c + 4)*40 + nt*8 + g];
                mma_tf32(oc[nt], a0, a1, a2, a3, b0, b1);
            }
        }
    }

    __syncthreads();
    #pragma unroll
    for (int nt = 0; nt < 4; ++nt) {
        float2 o;
        o.x = oc[nt][0]; o.y = oc[nt][1];
        *(float2*)(&w_tl[warp*544 + g*34 + nt*8 + c*2]) = o;
        o.x = oc[nt][2]; o.y = oc[nt][3];
        *(float2*)(&w_tl[warp*544 + (g+8)*34 + nt*8 + c*2]) = o;
    }
    __syncthreads();
    #pragma unroll
    for (int u = 0; u < 8; ++u) {
        int slot = t + u*256;
        int r = slot >> 5, d = slot & 31;
        int m4 = r >> 4, r16 = r & 15;
        float s = w_tl[m4*544 + r16*34 + d] + w_tl[(m4+4)*544 + r16*34 + d];
        Obuf[(size_t)(b*SS + q0 + r)*256 + coloff + d] = s;
    }
}

// ---------------- launch --------------------------------------------------
extern "C" void kernel_launch(void* const* d_in, const int* in_sizes, int n_in,
                              void* d_out, int out_size) {
    const float* v_ori = (const float*)d_in[0];
    const float* k_ori = (const float*)d_in[1];
    const float* q_ori = (const float*)d_in[2];
    const float* mask  = (const float*)d_in[3];
    const float* adj   = (const float*)d_in[4];
    const float* dist  = (const float*)d_in[5];
    const float* Wq_d = (const float*)d_in[6];  const float* bq_d = (const float*)d_in[7];
    const float* Wk_d = (const float*)d_in[8];  const float* bk_d = (const float*)d_in[9];
    const float* Wv_d = (const float*)d_in[10]; const float* bv_d = (const float*)d_in[11];
    const float* Wq_a = (const float*)d_in[12]; const float* bq_a = (const float*)d_in[13];
    const float* Wk_a = (const float*)d_in[14]; const float* bk_a = (const float*)d_in[15];
    const float* Wv_a = (const float*)d_in[16]; const float* bv_a = (const float*)d_in[17];
    const float* Wo   = (const float*)d_in[18]; const float* bo   = (const float*)d_in[19];

    float* out   = (float*)d_out;
    float* attnw = (out_size >= OUT_ELEMS + ATTN_ELEMS) ? out + OUT_ELEMS : (float*)0;

    float *pWq,*pWk,*pWv,*pbq,*pbk,*pbv,*pQ,*pK,*pV,*pKT,*pO,*pD;
    cudaGetSymbolAddress((void**)&pWq, g_Wq);
    cudaGetSymbolAddress((void**)&pWk, g_Wk);
    cudaGetSymbolAddress((void**)&pWv, g_Wv);
    cudaGetSymbolAddress((void**)&pbq, g_bq);
    cudaGetSymbolAddress((void**)&pbk, g_bk);
    cudaGetSymbolAddress((void**)&pbv, g_bv);
    cudaGetSymbolAddress((void**)&pQ,  g_Q);
    cudaGetSymbolAddress((void**)&pK,  g_K);
    cudaGetSymbolAddress((void**)&pV,  g_V);
    cudaGetSymbolAddress((void**)&pKT, g_KT);
    cudaGetSymbolAddress((void**)&pO,  g_O);
    cudaGetSymbolAddress((void**)&pD,  g_Dsm);

    const int GEMM_SMEM = 17664 * 4;   // 70,656 B
    cudaFuncSetAttribute(gemmT_kernel, cudaFuncAttributeMaxDynamicSharedMemorySize, GEMM_SMEM);
    const int ATTN_SMEM = 21440 * 4;   // 85,760 B
    cudaFuncSetAttribute(attn_kernel, cudaFuncAttributeMaxDynamicSharedMemorySize, ATTN_SMEM);

    // #0: fused pack
    pack3_kernel<<<dim3(256, 3), 256>>>(Wq_d, Wq_a, bq_d, bq_a,
                                        Wk_d, Wk_a, bk_d, bk_a,
                                        Wv_d, Wv_a, bv_d, bv_a,
                                        pWq, pbq, pWk, pbk, pWv, pbv);
    // #1-3: projections (tf32-split tensor-core GEMM)
    dim3 ggrid(128, 2);
    gemmT_kernel<<<ggrid, 256, GEMM_SMEM>>>(q_ori, pWq, pbq, pQ);
    gemmT_kernel<<<ggrid, 256, GEMM_SMEM>>>(k_ori, pWk, pbk, pK);
    gemmT_kernel<<<ggrid, 256, GEMM_SMEM>>>(v_ori, pWv, pbv, pV);

    // #4: fused dist-softmax + K-transpose
    prep_kernel<<<16384 + 4096, 256>>>(dist, mask, pK, pD, pKT);

    // #5: fused attention (two-pass streaming, mma.sync tf32)
    dim3 agrid(16, 8, 16);
    attn_kernel<<<agrid, 256, ATTN_SMEM>>>(pQ, pKT, pV, mask, pD, adj, attnw, pO);

    // #6: output projection
    gemmT_kernel<<<ggrid, 256, GEMM_SMEM>>>(pO, Wo, bo, out);
}

// round 8
// speedup vs baseline: 1.3429x; 1.3429x over previous
#include <cuda_runtime.h>
#include <cstddef>

// Problem constants
#define BB   16
#define SS   1024
#define DM   256
#define BSN  (BB*SS)             // 16384
#define OUT_ELEMS   (BSN*DM)     // 4,194,304
#define ATTN_ELEMS  (BB*8*SS*SS) // 134,217,728

typedef unsigned long long u64;

__device__ __forceinline__ u64 pk2(float x, float y) {
    u64 r; asm("mov.b64 %0, {%1,%2};" : "=l"(r) : "f"(x), "f"(y)); return r;
}
__device__ __forceinline__ void up2(u64 v, float& x, float& y) {
    asm("mov.b64 {%0,%1}, %2;" : "=f"(x), "=f"(y) : "l"(v));
}
__device__ __forceinline__ void ffma2(u64& d, u64 a, u64 b) {
    asm("fma.rn.f32x2 %0, %1, %2, %0;" : "+l"(d) : "l"(a), "l"(b));
}
__device__ __forceinline__ float to_tf32(float x) {
    float r; asm("cvt.rna.tf32.f32 %0, %1;" : "=f"(r) : "f"(x)); return r;
}
__device__ __forceinline__ void mma_tf32(float* d, float a0, float a1, float a2, float a3,
                                         float b0, float b1) {
    asm("mma.sync.aligned.m16n8k8.row.col.f32.tf32.tf32.f32 "
        "{%0,%1,%2,%3}, {%4,%5,%6,%7}, {%8,%9}, {%0,%1,%2,%3};"
        : "+f"(d[0]), "+f"(d[1]), "+f"(d[2]), "+f"(d[3])
        : "r"(__float_as_uint(a0)), "r"(__float_as_uint(a1)),
          "r"(__float_as_uint(a2)), "r"(__float_as_uint(a3)),
          "r"(__float_as_uint(b0)), "r"(__float_as_uint(b1)));
}

// ---------------- scratch (static device memory; no allocation) -------------
__device__ float g_Wq[256*256], g_Wk[256*256], g_Wv[256*256];
__device__ float g_bq[256],     g_bk[256],     g_bv[256];
__device__ float g_Q [BSN*DM];
__device__ float g_K [BSN*DM];
__device__ float g_V [BSN*DM];
__device__ float g_KT[BSN*DM];            // (b, n, s)
__device__ float g_O [BSN*DM];            // concat(o_dist, o_adj)
__device__ float g_Dsm[(size_t)BB*SS*SS]; // softmax(dist + neg)

// ---------------- fused weight packing ---------------------------------------
__global__ void pack3_kernel(
    const float* __restrict__ Wqd, const float* __restrict__ Wqa,
    const float* __restrict__ bqd, const float* __restrict__ bqa,
    const float* __restrict__ Wkd, const float* __restrict__ Wka,
    const float* __restrict__ bkd, const float* __restrict__ bka,
    const float* __restrict__ Wvd, const float* __restrict__ Wva,
    const float* __restrict__ bvd, const float* __restrict__ bva,
    float* __restrict__ Wq, float* __restrict__ bq,
    float* __restrict__ Wk, float* __restrict__ bk,
    float* __restrict__ Wv, float* __restrict__ bv) {
    int k = blockIdx.x, n = threadIdx.x, w = blockIdx.y;
    const float* Wd = (w == 0) ? Wqd : (w == 1) ? Wkd : Wvd;
    const float* Wa = (w == 0) ? Wqa : (w == 1) ? Wka : Wva;
    const float* bd = (w == 0) ? bqd : (w == 1) ? bkd : bvd;
    const float* ba = (w == 0) ? bqa : (w == 1) ? bka : bva;
    float* W    = (w == 0) ? Wq : (w == 1) ? Wk : Wv;
    float* bias = (w == 0) ? bq : (w == 1) ? bk : bv;
    W[k*256 + n] = (n < 128) ? Wd[k*128 + n] : Wa[k*128 + (n-128)];
    if (k == 0) bias[n] = (n < 128) ? bd[n] : ba[n-128];
}

// ---------------- GEMM (measured 58us): 128x128, FFMA2 ----------------------
__global__ __launch_bounds__(256)
void gemm2_kernel(const float* __restrict__ A, const float* __restrict__ W,
                  const float* __restrict__ bias, float* __restrict__ C) {
    __shared__ float As[16][132];
    __shared__ float Ws[16][132];
    const int t  = threadIdx.x;
    const int m0 = blockIdx.x * 128;
    const int n0 = blockIdx.y * 128;
    const int tn = t & 15, tm = t >> 4;

    u64 acc[4][8];
    #pragma unroll
    for (int p = 0; p < 4; ++p)
        #pragma unroll
        for (int j = 0; j < 8; ++j) acc[p][j] = 0ull;

    for (int k0 = 0; k0 < 256; k0 += 16) {
        __syncthreads();
        #pragma unroll
        for (int u = 0; u < 2; ++u) {
            int fi  = t + u*256;
            int row = fi >> 2, c4 = fi & 3;
            float4 v = *(const float4*)(A + (size_t)(m0+row)*256 + k0 + c4*4);
            As[c4*4+0][row] = v.x; As[c4*4+1][row] = v.y;
            As[c4*4+2][row] = v.z; As[c4*4+3][row] = v.w;
        }
        #pragma unroll
        for (int u = 0; u < 2; ++u) {
            int fi = t + u*256;
            int k = fi >> 5, n4 = fi & 31;
            *(float4*)(&Ws[k][n4*4]) =
                *(const float4*)(W + (size_t)(k0+k)*256 + n0 + n4*4);
        }
        __syncthreads();
        #pragma unroll
        for (int k = 0; k < 16; ++k) {
            ulonglong2 a01 = *(const ulonglong2*)(&As[k][tm*8]);
            ulonglong2 a23 = *(const ulonglong2*)(&As[k][tm*8 + 4]);
            u64 ap[4] = {a01.x, a01.y, a23.x, a23.y};
            float4 w0 = *(const float4*)(&Ws[k][tn*8]);
            float4 w1 = *(const float4*)(&Ws[k][tn*8 + 4]);
            u64 bd[8];
            bd[0] = pk2(w0.x, w0.x); bd[1] = pk2(w0.y, w0.y);
            bd[2] = pk2(w0.z, w0.z); bd[3] = pk2(w0.w, w0.w);
            bd[4] = pk2(w1.x, w1.x); bd[5] = pk2(w1.y, w1.y);
            bd[6] = pk2(w1.z, w1.z); bd[7] = pk2(w1.w, w1.w);
            #pragma unroll
            for (int p = 0; p < 4; ++p)
                #pragma unroll
                for (int j = 0; j < 8; ++j)
                    ffma2(acc[p][j], ap[p], bd[j]);
        }
    }
    float4 b0 = *(const float4*)(bias + n0 + tn*8);
    float4 b1 = *(const float4*)(bias + n0 + tn*8 + 4);
    float bb[8] = {b0.x, b0.y, b0.z, b0.w, b1.x, b1.y, b1.z, b1.w};
    #pragma unroll
    for (int p = 0; p < 4; ++p) {
        float lo[8], hi[8];
        #pragma unroll
        for (int j = 0; j < 8; ++j) up2(acc[p][j], lo[j], hi[j]);
        int r0 = m0 + tm*8 + p*2;
        float4 o;
        o.x = lo[0]+bb[0]; o.y = lo[1]+bb[1]; o.z = lo[2]+bb[2]; o.w = lo[3]+bb[3];
        *(float4*)(C + (size_t)r0*256 + n0 + tn*8) = o;
        o.x = lo[4]+bb[4]; o.y = lo[5]+bb[5]; o.z = lo[6]+bb[6]; o.w = lo[7]+bb[7];
        *(float4*)(C + (size_t)r0*256 + n0 + tn*8 + 4) = o;
        o.x = hi[0]+bb[0]; o.y = hi[1]+bb[1]; o.z = hi[2]+bb[2]; o.w = hi[3]+bb[3];
        *(float4*)(C + (size_t)(r0+1)*256 + n0 + tn*8) = o;
        o.x = hi[4]+bb[4]; o.y = hi[5]+bb[5]; o.z = hi[6]+bb[6]; o.w = hi[7]+bb[7];
        *(float4*)(C + (size_t)(r0+1)*256 + n0 + tn*8 + 4) = o;
    }
}

// ---------------- prep: dist softmax + K transpose (fused launch) -----------
__global__ __launch_bounds__(256)
void prep_kernel(const float* __restrict__ dist, const float* __restrict__ mask,
                 const float* __restrict__ Kp, float* __restrict__ Dsm,
                 float* __restrict__ KT) {
    __shared__ float tile[32][33];
    __shared__ float ws[8];
    const int blk = blockIdx.x;
    const int t = threadIdx.x;
    if (blk < 16384) {
        const int b = blk >> 10, q = blk & 1023;
        const float* drow = dist + ((size_t)b*SS + q)*SS;
        const float* mrow = mask + (size_t)b*SS;
        float e[4], s = 0.f;
        #pragma unroll
        for (int u = 0; u < 4; ++u) {
            int k = t + u*256;
            e[u] = __expf(drow[k] + mrow[k] * -1e9f);
            s += e[u];
        }
        #pragma unroll
        for (int off = 16; off; off >>= 1) s += __shfl_xor_sync(0xffffffffu, s, off);
        if ((t & 31) == 0) ws[t >> 5] = s;
        __syncthreads();
        float tot = 0.f;
        #pragma unroll
        for (int w = 0; w < 8; ++w) tot += ws[w];
        const float inv = 1.f / tot;
        float* orow = Dsm + ((size_t)b*SS + q)*SS;
        #pragma unroll
        for (int u = 0; u < 4; ++u) orow[t + u*256] = e[u] * inv;
    } else {
        const int r  = (blk - 16384) & 255;
        const int b  = (blk - 16384) >> 8;
        const int n0 = (r & 7) * 32;
        const int s0 = (r >> 3) * 32;
        const int tx = t & 31, ty = t >> 5;
        const float* src = Kp + ((size_t)b*SS + s0)*256 + n0;
        #pragma unroll
        for (int i = 0; i < 32; i += 8)
            tile[ty+i][tx] = src[(size_t)(ty+i)*256 + tx];
        __syncthreads();
        float* dst = KT + ((size_t)b*256 + n0)*SS + s0;
        #pragma unroll
        for (int i = 0; i < 32; i += 8)
            dst[(size_t)(ty+i)*SS + tx] = tile[tx][ty+i];
    }
}

// ---------------- fused attention: 64 q/CTA, two-pass, pipelined loads ------
// K double-buffered in smem; next-tile K (and current-tile V in pass 2) are
// prefetched into REGISTERS at the top of each tile iteration, STS'd after the
// mma block -> LDG latency hidden under tensor work.
// smem floats: q_sm 2304 | k_sm 2x4352 | v_sm 5120 | w_tl 8448 | msk 1024 |
// redu 192.  Total 25792 fl = 103,168 B -> 2 CTAs/SM.
__global__ __launch_bounds__(256, 2)
void attn_kernel(const float* __restrict__ Q, const float* __restrict__ KT,
                 const float* __restrict__ V, const float* __restrict__ mask,
                 const float* __restrict__ extraD, const float* __restrict__ extraA,
                 float* __restrict__ attnw, float* __restrict__ Obuf) {
    extern __shared__ float sm[];
    float* q_sm = sm;              // 2304
    float* k_s0 = sm + 2304;       // 4352 (stride 136)
    float* k_s1 = sm + 6656;       // 4352
    float* v_sm = sm + 11008;      // 5120 (stride 40)
    float* w_tl = sm + 16128;      // 8448 (stride 132; reused as partials 8x544)
    float* msk  = sm + 24576;      // 1024
    float* redu = sm + 25600;      // 192

    const int t    = threadIdx.x;
    const int lane = t & 31, warp = t >> 5;
    const int g = lane >> 2, c = lane & 3;
    const int mq = warp & 3, nh = warp >> 2;
    const int q0 = blockIdx.x * 64;
    const int hg = blockIdx.y;
    const int b  = blockIdx.z;
    const int coloff = hg * 32;
    const float* extra = (hg >= 4) ? extraA : extraD;

    #pragma unroll
    for (int u = 0; u < 8; ++u) {
        int i = t + u*256;
        int r = i >> 5, d = i & 31;
        q_sm[r*36 + d] = to_tf32(Q[(size_t)(b*SS + q0 + r)*256 + coloff + d]);
    }
    #pragma unroll
    for (int u = 0; u < 4; ++u)
        msk[t + u*256] = mask[b*SS + t + u*256] * -1e9f;

    const float* ktb   = KT + ((size_t)b*256 + coloff)*SS;
    const float* vbase = V + (size_t)b*SS*256 + coloff;
    const float scale = 0.17677669529663688f;

    const int rlo = mq*16 + g;
    const int rhi = rlo + 8;

    float* kbuf[2] = {k_s0, k_s1};

    // =================== PASS 1: row sums ===================
    {
        #pragma unroll
        for (int u = 0; u < 4; ++u) {
            int fi = t + u*256;
            int kd = fi >> 5, c4 = fi & 31;
            float4 v = *(const float4*)(ktb + (size_t)kd*SS + c4*4);
            v.x = to_tf32(v.x); v.y = to_tf32(v.y);
            v.z = to_tf32(v.z); v.w = to_tf32(v.w);
            *(float4*)(&k_s0[kd*136 + c4*4]) = v;
        }
    }
    __syncthreads();

    float s_lo = 0.f, s_hi = 0.f;
    for (int tile = 0; tile < 8; ++tile) {
        const int cur = tile & 1;
        const float* ksm = kbuf[cur];
        float4 kpre[4];
        if (tile < 7) {
            #pragma unroll
            for (int u = 0; u < 4; ++u) {
                int fi = t + u*256;
                int kd = fi >> 5, c4 = fi & 31;
                kpre[u] = *(const float4*)(ktb + (size_t)kd*SS + (tile+1)*128 + c4*4);
            }
        }
        float acc[8][4];
        #pragma unroll
        for (int nt = 0; nt < 8; ++nt)
            #pragma unroll
            for (int j = 0; j < 4; ++j) acc[nt][j] = 0.f;
        #pragma unroll
        for (int ks = 0; ks < 4; ++ks) {
            float a0 = q_sm[rlo*36 + ks*8 + c];
            float a1 = q_sm[rhi*36 + ks*8 + c];
            float a2 = q_sm[rlo*36 + ks*8 + c + 4];
            float a3 = q_sm[rhi*36 + ks*8 + c + 4];
            #pragma unroll
            for (int nt = 0; nt < 8; ++nt) {
                int n0 = nh*64 + nt*8 + g;
                float b0 = ksm[(ks*8 + c)*136 + n0];
                float b1 = ksm[(ks*8 + c + 4)*136 + n0];
                mma_tf32(acc[nt], a0, a1, a2, a3, b0, b1);
            }
        }
        #pragma unroll
        for (int nt = 0; nt < 8; ++nt) {
            int key0 = tile*128 + nh*64 + nt*8 + c*2;
            float n0v = msk[key0], n1v = msk[key0+1];
            s_lo += __expf(fmaf(acc[nt][0], scale, n0v));
            s_lo += __expf(fmaf(acc[nt][1], scale, n1v));
            s_hi += __expf(fmaf(acc[nt][2], scale, n0v));
            s_hi += __expf(fmaf(acc[nt][3], scale, n1v));
        }
        if (tile < 7) {
            float* dst = kbuf[cur ^ 1];
            #pragma unroll
            for (int u = 0; u < 4; ++u) {
                int fi = t + u*256;
                int kd = fi >> 5, c4 = fi & 31;
                float4 v = kpre[u];
                v.x = to_tf32(v.x); v.y = to_tf32(v.y);
                v.z = to_tf32(v.z); v.w = to_tf32(v.w);
                *(float4*)(&dst[kd*136 + c4*4]) = v;
            }
        }
        __syncthreads();
    }
    s_lo += __shfl_xor_sync(0xffffffffu, s_lo, 1);
    s_lo += __shfl_xor_sync(0xffffffffu, s_lo, 2);
    s_hi += __shfl_xor_sync(0xffffffffu, s_hi, 1);
    s_hi += __shfl_xor_sync(0xffffffffu, s_hi, 2);
    if (c == 0) {
        redu[nh*64 + rlo] = s_lo;
        redu[nh*64 + rhi] = s_hi;
    }
    __syncthreads();
    if (t < 64) redu[128 + t] = 1.f / (redu[t] + redu[64 + t]);

    const float* exlo = extra + ((size_t)b*SS + q0 + rlo)*SS;
    const float* exhi = extra + ((size_t)b*SS + q0 + rhi)*SS;
    float* wplo = attnw ? attnw + ((size_t)(b*8 + hg)*SS + q0 + rlo)*SS : (float*)0;
    float* wphi = attnw ? attnw + ((size_t)(b*8 + hg)*SS + q0 + rhi)*SS : (float*)0;

    // =================== PASS 2: weights + PV ===================
    float oc[4][4];
    #pragma unroll
    for (int nt = 0; nt < 4; ++nt)
        #pragma unroll
        for (int j = 0; j < 4; ++j) oc[nt][j] = 0.f;

    // prologue: stage K tile 0 again (disjoint from redu)
    {
        #pragma unroll
        for (int u = 0; u < 4; ++u) {
            int fi = t + u*256;
            int kd = fi >> 5, c4 = fi & 31;
            float4 v = *(const float4*)(ktb + (size_t)kd*SS + c4*4);
            v.x = to_tf32(v.x); v.y = to_tf32(v.y);
            v.z = to_tf32(v.z); v.w = to_tf32(v.w);
            *(float4*)(&k_s0[kd*136 + c4*4]) = v;
        }
    }
    __syncthreads();                  // redu[128+] and k_s0 now visible to all
    const float inv_lo = redu[128 + rlo];
    const float inv_hi = redu[128 + rhi];

    for (int tile = 0; tile < 8; ++tile) {
        const int cur = tile & 1;
        const float* ksm = kbuf[cur];
        // prefetch: V(tile) + K(tile+1) into registers
        float4 vpre[4], kpre[4];
        #pragma unroll
        for (int u = 0; u < 4; ++u) {
            int fi = t + u*256;
            int kr = fi >> 3, q4 = fi & 7;
            vpre[u] = *(const float4*)(vbase + (size_t)(tile*128 + kr)*256 + q4*4);
        }
        if (tile < 7) {
            #pragma unroll
            for (int u = 0; u < 4; ++u) {
                int fi = t + u*256;
                int kd = fi >> 5, c4 = fi & 31;
                kpre[u] = *(const float4*)(ktb + (size_t)kd*SS + (tile+1)*128 + c4*4);
            }
        }
        // QK mma from current K tile (hides prefetch latency)
        float acc[8][4];
        #pragma unroll
        for (int nt = 0; nt < 8; ++nt)
            #pragma unroll
            for (int j = 0; j < 4; ++j) acc[nt][j] = 0.f;
        #pragma unroll
        for (int ks = 0; ks < 4; ++ks) {
            float a0 = q_sm[rlo*36 + ks*8 + c];
            float a1 = q_sm[rhi*36 + ks*8 + c];
            float a2 = q_sm[rlo*36 + ks*8 + c + 4];
            float a3 = q_sm[rhi*36 + ks*8 + c + 4];
            #pragma unroll
            for (int nt = 0; nt < 8; ++nt) {
                int n0 = nh*64 + nt*8 + g;
                float b0 = ksm[(ks*8 + c)*136 + n0];
                float b1 = ksm[(ks*8 + c + 4)*136 + n0];
                mma_tf32(acc[nt], a0, a1, a2, a3, b0, b1);
            }
        }
        // drain prefetches to smem
        #pragma unroll
        for (int u = 0; u < 4; ++u) {
            int fi = t + u*256;
            int kr = fi >> 3, q4 = fi & 7;
            float4 v = vpre[u];
            v.x = to_tf32(v.x); v.y = to_tf32(v.y);
            v.z = to_tf32(v.z); v.w = to_tf32(v.w);
            *(float4*)(&v_sm[kr*40 + q4*4]) = v;
        }
        if (tile < 7) {
            float* dst = kbuf[cur ^ 1];
            #pragma unroll
            for (int u = 0; u < 4; ++u) {
                int fi = t + u*256;
                int kd = fi >> 5, c4 = fi & 31;
                float4 v = kpre[u];
                v.x = to_tf32(v.x); v.y = to_tf32(v.y);
                v.z = to_tf32(v.z); v.w = to_tf32(v.w);
                *(float4*)(&dst[kd*136 + c4*4]) = v;
            }
        }
        // w = exp(...)*inv*extra -> attn_w + w_tl
        #pragma unroll
        for (int nt = 0; nt < 8; ++nt) {
            int lkey = nh*64 + nt*8 + c*2;
            int key0 = tile*128 + lkey;
            float n0v = msk[key0], n1v = msk[key0+1];
            float2 elo = *(const float2*)(exlo + key0);
            float2 ehi = *(const float2*)(exhi + key0);
            float w0 = __expf(fmaf(acc[nt][0], scale, n0v)) * inv_lo * elo.x;
            float w1 = __expf(fmaf(acc[nt][1], scale, n1v)) * inv_lo * elo.y;
            float w2 = __expf(fmaf(acc[nt][2], scale, n0v)) * inv_hi * ehi.x;
            float w3 = __expf(fmaf(acc[nt][3], scale, n1v)) * inv_hi * ehi.y;
            if (wplo) {
                float2 o; o.x = w0; o.y = w1; *(float2*)(wplo + key0) = o;
                o.x = w2; o.y = w3; *(float2*)(wphi + key0) = o;
            }
            float2 s;
            s.x = to_tf32(w0); s.y = to_tf32(w1);
            *(float2*)(&w_tl[rlo*132 + lkey]) = s;
            s.x = to_tf32(w2); s.y = to_tf32(w3);
            *(float2*)(&w_tl[rhi*132 + lkey]) = s;
        }
        __syncthreads();   // v_sm, w_tl, next K ready
        // PV mma
        #pragma unroll
        for (int ks = 0; ks < 8; ++ks) {
            int kb = nh*64 + ks*8;
            float a0 = w_tl[rlo*132 + kb + c];
            float a1 = w_tl[rhi*132 + kb + c];
            float a2 = w_tl[rlo*132 + kb + c + 4];
            float a3 = w_tl[rhi*132 + kb + c + 4];
            #pragma unroll
            for (int nt = 0; nt < 4; ++nt) {
                float b0 = v_sm[(kb + c)*40 + nt*8 + g];
                float b1 = v_sm[(kb + c + 4)*40 + nt*8 + g];
                mma_tf32(oc[nt], a0, a1, a2, a3, b0, b1);
            }
        }
        __syncthreads();   // PV done before v_sm/w_tl overwrite next tile
    }

    // ---- cross-half key reduction via smem ----
    #pragma unroll
    for (int nt = 0; nt < 4; ++nt) {
        float2 o;
        o.x = oc[nt][0]; o.y = oc[nt][1];
        *(float2*)(&w_tl[warp*544 + g*34 + nt*8 + c*2]) = o;
        o.x = oc[nt][2]; o.y = oc[nt][3];
        *(float2*)(&w_tl[warp*544 + (g+8)*34 + nt*8 + c*2]) = o;
    }
    __syncthreads();
    #pragma unroll
    for (int u = 0; u < 8; ++u) {
        int slot = t + u*256;
        int r = slot >> 5, d = slot & 31;
        int m4 = r >> 4, r16 = r & 15;
        float s = w_tl[m4*544 + r16*34 + d] + w_tl[(m4+4)*544 + r16*34 + d];
        Obuf[(size_t)(b*SS + q0 + r)*256 + coloff + d] = s;
    }
}

// ---------------- launch --------------------------------------------------
extern "C" void kernel_launch(void* const* d_in, const int* in_sizes, int n_in,
                              void* d_out, int out_size) {
    const float* v_ori = (const float*)d_in[0];
    const float* k_ori = (const float*)d_in[1];
    const float* q_ori = (const float*)d_in[2];
    const float* mask  = (const float*)d_in[3];
    const float* adj   = (const float*)d_in[4];
    const float* dist  = (const float*)d_in[5];
    const float* Wq_d = (const float*)d_in[6];  const float* bq_d = (const float*)d_in[7];
    const float* Wk_d = (const float*)d_in[8];  const float* bk_d = (const float*)d_in[9];
    const float* Wv_d = (const float*)d_in[10]; const float* bv_d = (const float*)d_in[11];
    const float* Wq_a = (const float*)d_in[12]; const float* bq_a = (const float*)d_in[13];
    const float* Wk_a = (const float*)d_in[14]; const float* bk_a = (const float*)d_in[15];
    const float* Wv_a = (const float*)d_in[16]; const float* bv_a = (const float*)d_in[17];
    const float* Wo   = (const float*)d_in[18]; const float* bo   = (const float*)d_in[19];

    float* out   = (float*)d_out;
    float* attnw = (out_size >= OUT_ELEMS + ATTN_ELEMS) ? out + OUT_ELEMS : (float*)0;

    float *pWq,*pWk,*pWv,*pbq,*pbk,*pbv,*pQ,*pK,*pV,*pKT,*pO,*pD;
    cudaGetSymbolAddress((void**)&pWq, g_Wq);
    cudaGetSymbolAddress((void**)&pWk, g_Wk);
    cudaGetSymbolAddress((void**)&pWv, g_Wv);
    cudaGetSymbolAddress((void**)&pbq, g_bq);
    cudaGetSymbolAddress((void**)&pbk, g_bk);
    cudaGetSymbolAddress((void**)&pbv, g_bv);
    cudaGetSymbolAddress((void**)&pQ,  g_Q);
    cudaGetSymbolAddress((void**)&pK,  g_K);
    cudaGetSymbolAddress((void**)&pV,  g_V);
    cudaGetSymbolAddress((void**)&pKT, g_KT);
    cudaGetSymbolAddress((void**)&pO,  g_O);
    cudaGetSymbolAddress((void**)&pD,  g_Dsm);

    const int ATTN_SMEM = 25792 * 4;   // 103,168 B -> 2 CTAs/SM
    cudaFuncSetAttribute(attn_kernel, cudaFuncAttributeMaxDynamicSharedMemorySize, ATTN_SMEM);

    // #0: fused pack
    pack3_kernel<<<dim3(256, 3), 256>>>(Wq_d, Wq_a, bq_d, bq_a,
                                        Wk_d, Wk_a, bk_d, bk_a,
                                        Wv_d, Wv_a, bv_d, bv_a,
                                        pWq, pbq, pWk, pbk, pWv, pbv);
    // #1-3: projections
    dim3 ggrid(128, 2);
    gemm2_kernel<<<ggrid, 256>>>(q_ori, pWq, pbq, pQ);
    gemm2_kernel<<<ggrid, 256>>>(k_ori, pWk, pbk, pK);
    gemm2_kernel<<<ggrid, 256>>>(v_ori, pWv, pbv, pV);

    // #4: fused dist-softmax + K-transpose
    prep_kernel<<<16384 + 4096, 256>>>(dist, mask, pK, pD, pKT);

    // #5: fused attention (two-pass streaming, pipelined loads, mma.sync tf32)
    dim3 agrid(16, 8, 16);
    attn_kernel<<<agrid, 256, ATTN_SMEM>>>(pQ, pKT, pV, mask, pD, adj, attnw, pO);

    // #6: output projection
    gemm2_kernel<<<ggrid, 256>>>(pO, Wo, bo, out);
}

// round 9
// speedup vs baseline: 1.4339x; 1.0678x over previous
#include <cuda_runtime.h>
#include <cstddef>
#include <cstdint>

// Problem constants
#define BB   16
#define SS   1024
#define DM   256
#define BSN  (BB*SS)             // 16384
#define OUT_ELEMS   (BSN*DM)     // 4,194,304
#define ATTN_ELEMS  (BB*8*SS*SS) // 134,217,728

typedef unsigned long long u64;

__device__ __forceinline__ u64 pk2(float x, float y) {
    u64 r; asm("mov.b64 %0, {%1,%2};" : "=l"(r) : "f"(x), "f"(y)); return r;
}
__device__ __forceinline__ void up2(u64 v, float& x, float& y) {
    asm("mov.b64 {%0,%1}, %2;" : "=f"(x), "=f"(y) : "l"(v));
}
__device__ __forceinline__ void ffma2(u64& d, u64 a, u64 b) {
    asm("fma.rn.f32x2 %0, %1, %2, %0;" : "+l"(d) : "l"(a), "l"(b));
}
__device__ __forceinline__ float to_tf32(float x) {
    float r; asm("cvt.rna.tf32.f32 %0, %1;" : "=f"(r) : "f"(x)); return r;
}
__device__ __forceinline__ void mma_tf32(float* d, float a0, float a1, float a2, float a3,
                                         float b0, float b1) {
    asm("mma.sync.aligned.m16n8k8.row.col.f32.tf32.tf32.f32 "
        "{%0,%1,%2,%3}, {%4,%5,%6,%7}, {%8,%9}, {%0,%1,%2,%3};"
        : "+f"(d[0]), "+f"(d[1]), "+f"(d[2]), "+f"(d[3])
        : "r"(__float_as_uint(a0)), "r"(__float_as_uint(a1)),
          "r"(__float_as_uint(a2)), "r"(__float_as_uint(a3)),
          "r"(__float_as_uint(b0)), "r"(__float_as_uint(b1)));
}
__device__ __forceinline__ void cp16(float* smem, const float* gmem) {
    uint32_t s = (uint32_t)__cvta_generic_to_shared(smem);
    asm volatile("cp.async.cg.shared.global [%0], [%1], 16;" :: "r"(s), "l"(gmem));
}
#define CP_COMMIT() asm volatile("cp.async.commit_group;" ::: "memory")
#define CP_WAIT0()  asm volatile("cp.async.wait_group 0;" ::: "memory")

// ---------------- scratch (static device memory; no allocation) -------------
__device__ float g_Wq[256*256], g_Wk[256*256], g_Wv[256*256];
__device__ float g_bq[256],     g_bk[256],     g_bv[256];
__device__ float g_Q [BSN*DM];
__device__ float g_K [BSN*DM];
__device__ float g_V [BSN*DM];
__device__ float g_KT[BSN*DM];            // (b, n, s)  tf32-rounded
__device__ float g_O [BSN*DM];            // concat(o_dist, o_adj)
__device__ float g_Dsm[(size_t)BB*SS*SS]; // softmax(dist + neg)

// ---------------- fused weight packing ---------------------------------------
__global__ void pack3_kernel(
    const float* __restrict__ Wqd, const float* __restrict__ Wqa,
    const float* __restrict__ bqd, const float* __restrict__ bqa,
    const float* __restrict__ Wkd, const float* __restrict__ Wka,
    const float* __restrict__ bkd, const float* __restrict__ bka,
    const float* __restrict__ Wvd, const float* __restrict__ Wva,
    const float* __restrict__ bvd, const float* __restrict__ bva,
    float* __restrict__ Wq, float* __restrict__ bq,
    float* __restrict__ Wk, float* __restrict__ bk,
    float* __restrict__ Wv, float* __restrict__ bv) {
    int k = blockIdx.x, n = threadIdx.x, w = blockIdx.y;
    const float* Wd = (w == 0) ? Wqd : (w == 1) ? Wkd : Wvd;
    const float* Wa = (w == 0) ? Wqa : (w == 1) ? Wka : Wva;
    const float* bd = (w == 0) ? bqd : (w == 1) ? bkd : bvd;
    const float* ba = (w == 0) ? bqa : (w == 1) ? bka : bva;
    float* W    = (w == 0) ? Wq : (w == 1) ? Wk : Wv;
    float* bias = (w == 0) ? bq : (w == 1) ? bk : bv;
    W[k*256 + n] = (n < 128) ? Wd[k*128 + n] : Wa[k*128 + (n-128)];
    if (k == 0) bias[n] = (n < 128) ? bd[n] : ba[n-128];
}

// ---------------- GEMM (measured 58us): 128x128, FFMA2 ----------------------
__global__ __launch_bounds__(256)
void gemm2_kernel(const float* __restrict__ A, const float* __restrict__ W,
                  const float* __restrict__ bias, float* __restrict__ C) {
    __shared__ float As[16][132];
    __shared__ float Ws[16][132];
    const int t  = threadIdx.x;
    const int m0 = blockIdx.x * 128;
    const int n0 = blockIdx.y * 128;
    const int tn = t & 15, tm = t >> 4;

    u64 acc[4][8];
    #pragma unroll
    for (int p = 0; p < 4; ++p)
        #pragma unroll
        for (int j = 0; j < 8; ++j) acc[p][j] = 0ull;

    for (int k0 = 0; k0 < 256; k0 += 16) {
        __syncthreads();
        #pragma unroll
        for (int u = 0; u < 2; ++u) {
            int fi  = t + u*256;
            int row = fi >> 2, c4 = fi & 3;
            float4 v = *(const float4*)(A + (size_t)(m0+row)*256 + k0 + c4*4);
            As[c4*4+0][row] = v.x; As[c4*4+1][row] = v.y;
            As[c4*4+2][row] = v.z; As[c4*4+3][row] = v.w;
        }
        #pragma unroll
        for (int u = 0; u < 2; ++u) {
            int fi = t + u*256;
            int k = fi >> 5, n4 = fi & 31;
            *(float4*)(&Ws[k][n4*4]) =
                *(const float4*)(W + (size_t)(k0+k)*256 + n0 + n4*4);
        }
        __syncthreads();
        #pragma unroll
        for (int k = 0; k < 16; ++k) {
            ulonglong2 a01 = *(const ulonglong2*)(&As[k][tm*8]);
            ulonglong2 a23 = *(const ulonglong2*)(&As[k][tm*8 + 4]);
            u64 ap[4] = {a01.x, a01.y, a23.x, a23.y};
            float4 w0 = *(const float4*)(&Ws[k][tn*8]);
            float4 w1 = *(const float4*)(&Ws[k][tn*8 + 4]);
            u64 bd[8];
            bd[0] = pk2(w0.x, w0.x); bd[1] = pk2(w0.y, w0.y);
            bd[2] = pk2(w0.z, w0.z); bd[3] = pk2(w0.w, w0.w);
            bd[4] = pk2(w1.x, w1.x); bd[5] = pk2(w1.y, w1.y);
            bd[6] = pk2(w1.z, w1.z); bd[7] = pk2(w1.w, w1.w);
            #pragma unroll
            for (int p = 0; p < 4; ++p)
                #pragma unroll
                for (int j = 0; j < 8; ++j)
                    ffma2(acc[p][j], ap[p], bd[j]);
        }
    }
    float4 b0 = *(const float4*)(bias + n0 + tn*8);
    float4 b1 = *(const float4*)(bias + n0 + tn*8 + 4);
    float bb[8] = {b0.x, b0.y, b0.z, b0.w, b1.x, b1.y, b1.z, b1.w};
    #pragma unroll
    for (int p = 0; p < 4; ++p) {
        float lo[8], hi[8];
        #pragma unroll
        for (int j = 0; j < 8; ++j) up2(acc[p][j], lo[j], hi[j]);
        int r0 = m0 + tm*8 + p*2;
        float4 o;
        o.x = lo[0]+bb[0]; o.y = lo[1]+bb[1]; o.z = lo[2]+bb[2]; o.w = lo[3]+bb[3];
        *(float4*)(C + (size_t)r0*256 + n0 + tn*8) = o;
        o.x = lo[4]+bb[4]; o.y = lo[5]+bb[5]; o.z = lo[6]+bb[6]; o.w = lo[7]+bb[7];
        *(float4*)(C + (size_t)r0*256 + n0 + tn*8 + 4) = o;
        o.x = hi[0]+bb[0]; o.y = hi[1]+bb[1]; o.z = hi[2]+bb[2]; o.w = hi[3]+bb[3];
        *(float4*)(C + (size_t)(r0+1)*256 + n0 + tn*8) = o;
        o.x = hi[4]+bb[4]; o.y = hi[5]+bb[5]; o.z = hi[6]+bb[6]; o.w = hi[7]+bb[7];
        *(float4*)(C + (size_t)(r0+1)*256 + n0 + tn*8 + 4) = o;
    }
}

// ---------------- prep: dist softmax + K transpose(tf32) + V round ----------
__global__ __launch_bounds__(256)
void prep_kernel(const float* __restrict__ dist, const float* __restrict__ mask,
                 const float* __restrict__ Kp, float* __restrict__ Dsm,
                 float* __restrict__ KT, float* __restrict__ Vbuf) {
    __shared__ float tile[32][33];
    __shared__ float ws[8];
    const int blk = blockIdx.x;
    const int t = threadIdx.x;
    if (blk < 16384) {
        const int b = blk >> 10, q = blk & 1023;
        const float* drow = dist + ((size_t)b*SS + q)*SS;
        const float* mrow = mask + (size_t)b*SS;
        float e[4], s = 0.f;
        #pragma unroll
        for (int u = 0; u < 4; ++u) {
            int k = t + u*256;
            e[u] = __expf(drow[k] + mrow[k] * -1e9f);
            s += e[u];
        }
        #pragma unroll
        for (int off = 16; off; off >>= 1) s += __shfl_xor_sync(0xffffffffu, s, off);
        if ((t & 31) == 0) ws[t >> 5] = s;
        __syncthreads();
        float tot = 0.f;
        #pragma unroll
        for (int w = 0; w < 8; ++w) tot += ws[w];
        const float inv = 1.f / tot;
        float* orow = Dsm + ((size_t)b*SS + q)*SS;
        #pragma unroll
        for (int u = 0; u < 4; ++u) orow[t + u*256] = e[u] * inv;
    } else if (blk < 16384 + 4096) {
        // K transpose (writes tf32-rounded KT)
        const int r  = (blk - 16384) & 255;
        const int b  = (blk - 16384) >> 8;
        const int n0 = (r & 7) * 32;
        const int s0 = (r >> 3) * 32;
        const int tx = t & 31, ty = t >> 5;
        const float* src = Kp + ((size_t)b*SS + s0)*256 + n0;
        #pragma unroll
        for (int i = 0; i < 32; i += 8)
            tile[ty+i][tx] = src[(size_t)(ty+i)*256 + tx];
        __syncthreads();
        float* dst = KT + ((size_t)b*256 + n0)*SS + s0;
        #pragma unroll
        for (int i = 0; i < 32; i += 8)
            dst[(size_t)(ty+i)*SS + tx] = to_tf32(tile[tx][ty+i]);
    } else {
        // round V in place to tf32 (idempotent)
        int i = (blk - 16384 - 4096) * 256 + t;   // float4 index
        float4* Vp = (float4*)Vbuf;
        float4 v = Vp[i];
        v.x = to_tf32(v.x); v.y = to_tf32(v.y);
        v.z = to_tf32(v.z); v.w = to_tf32(v.w);
        Vp[i] = v;
    }
}

// ---------------- fused attention: 64 q/CTA, two-pass, cp.async pipelining --
// K double-buffered via cp.async (zero register cost); V cp.async'd at pass-2
// loop top and waited just before PV. KT/V are pre-rounded to tf32 upstream.
// smem floats: q_sm 2304 | k 2x4352 | v_sm 5120 | w_tl 8448 | msk 1024 |
// redu 192.  Total 25792 fl = 103,168 B -> 2 CTAs/SM.
__global__ __launch_bounds__(256, 2)
void attn_kernel(const float* __restrict__ Q, const float* __restrict__ KT,
                 const float* __restrict__ V, const float* __restrict__ mask,
                 const float* __restrict__ extraD, const float* __restrict__ extraA,
                 float* __restrict__ attnw, float* __restrict__ Obuf) {
    extern __shared__ float sm[];
    float* q_sm = sm;              // 2304
    float* k_s0 = sm + 2304;       // 4352 (stride 136)
    float* k_s1 = sm + 6656;       // 4352
    float* v_sm = sm + 11008;      // 5120 (stride 40)
    float* w_tl = sm + 16128;      // 8448 (stride 132; reused as partials 8x544)
    float* msk  = sm + 24576;      // 1024
    float* redu = sm + 25600;      // 192

    const int t    = threadIdx.x;
    const int lane = t & 31, warp = t >> 5;
    const int g = lane >> 2, c = lane & 3;
    const int mq = warp & 3, nh = warp >> 2;
    const int q0 = blockIdx.x * 64;
    const int hg = blockIdx.y;
    const int b  = blockIdx.z;
    const int coloff = hg * 32;
    const float* extra = (hg >= 4) ? extraA : extraD;

    // loader indices (4x 16B per thread for both K and V tiles)
    const int lk_d = t >> 5;                 // base K dim row (0..7), +8 per u... (recomputed per u)
    #pragma unroll
    for (int u = 0; u < 8; ++u) {
        int i = t + u*256;
        int r = i >> 5, d = i & 31;
        q_sm[r*36 + d] = to_tf32(Q[(size_t)(b*SS + q0 + r)*256 + coloff + d]);
    }
    #pragma unroll
    for (int u = 0; u < 4; ++u)
        msk[t + u*256] = mask[b*SS + t + u*256] * -1e9f;

    const float* ktb   = KT + ((size_t)b*256 + coloff)*SS;
    const float* vbase = V + (size_t)b*SS*256 + coloff;
    const float scale = 0.17677669529663688f;

    const int rlo = mq*16 + g;
    const int rhi = rlo + 8;
    (void)lk_d;

    float* kbuf[2] = {k_s0, k_s1};

    // =================== PASS 1: row sums ===================
    // prologue: cp.async K tile 0
    #pragma unroll
    for (int u = 0; u < 4; ++u) {
        int fi = t + u*256;
        int kd = fi >> 5, c4 = fi & 31;
        cp16(&k_s0[kd*136 + c4*4], ktb + (size_t)kd*SS + c4*4);
    }
    CP_COMMIT(); CP_WAIT0();
    __syncthreads();

    float s_lo = 0.f, s_hi = 0.f;
    for (int tile = 0; tile < 8; ++tile) {
        const int cur = tile & 1;
        const float* ksm = kbuf[cur];
        if (tile < 7) {
            float* dst = kbuf[cur ^ 1];
            #pragma unroll
            for (int u = 0; u < 4; ++u) {
                int fi = t + u*256;
                int kd = fi >> 5, c4 = fi & 31;
                cp16(&dst[kd*136 + c4*4], ktb + (size_t)kd*SS + (tile+1)*128 + c4*4);
            }
            CP_COMMIT();
        }
        float acc[8][4];
        #pragma unroll
        for (int nt = 0; nt < 8; ++nt)
            #pragma unroll
            for (int j = 0; j < 4; ++j) acc[nt][j] = 0.f;
        #pragma unroll
        for (int ks = 0; ks < 4; ++ks) {
            float a0 = q_sm[rlo*36 + ks*8 + c];
            float a1 = q_sm[rhi*36 + ks*8 + c];
            float a2 = q_sm[rlo*36 + ks*8 + c + 4];
            float a3 = q_sm[rhi*36 + ks*8 + c + 4];
            #pragma unroll
            for (int nt = 0; nt < 8; ++nt) {
                int n0 = nh*64 + nt*8 + g;
                float b0 = ksm[(ks*8 + c)*136 + n0];
                float b1 = ksm[(ks*8 + c + 4)*136 + n0];
                mma_tf32(acc[nt], a0, a1, a2, a3, b0, b1);
            }
        }
        #pragma unroll
        for (int nt = 0; nt < 8; ++nt) {
            int key0 = tile*128 + nh*64 + nt*8 + c*2;
            float n0v = msk[key0], n1v = msk[key0+1];
            s_lo += __expf(fmaf(acc[nt][0], scale, n0v));
            s_lo += __expf(fmaf(acc[nt][1], scale, n1v));
            s_hi += __expf(fmaf(acc[nt][2], scale, n0v));
            s_hi += __expf(fmaf(acc[nt][3], scale, n1v));
        }
        if (tile < 7) CP_WAIT0();
        __syncthreads();
    }
    s_lo += __shfl_xor_sync(0xffffffffu, s_lo, 1);
    s_lo += __shfl_xor_sync(0xffffffffu, s_lo, 2);
    s_hi += __shfl_xor_sync(0xffffffffu, s_hi, 1);
    s_hi += __shfl_xor_sync(0xffffffffu, s_hi, 2);
    if (c == 0) {
        redu[nh*64 + rlo] = s_lo;
        redu[nh*64 + rhi] = s_hi;
    }
    __syncthreads();
    if (t < 64) redu[128 + t] = 1.f / (redu[t] + redu[64 + t]);

    const float* exlo = extra + ((size_t)b*SS + q0 + rlo)*SS;
    const float* exhi = extra + ((size_t)b*SS + q0 + rhi)*SS;
    float* wplo = attnw ? attnw + ((size_t)(b*8 + hg)*SS + q0 + rlo)*SS : (float*)0;
    float* wphi = attnw ? attnw + ((size_t)(b*8 + hg)*SS + q0 + rhi)*SS : (float*)0;

    // =================== PASS 2: weights + PV ===================
    float oc[4][4];
    #pragma unroll
    for (int nt = 0; nt < 4; ++nt)
        #pragma unroll
        for (int j = 0; j < 4; ++j) oc[nt][j] = 0.f;

    // prologue: cp.async K tile 0 (k_s0 free; disjoint from redu)
    #pragma unroll
    for (int u = 0; u < 4; ++u) {
        int fi = t + u*256;
        int kd = fi >> 5, c4 = fi & 31;
        cp16(&k_s0[kd*136 + c4*4], ktb + (size_t)kd*SS + c4*4);
    }
    CP_COMMIT(); CP_WAIT0();
    __syncthreads();                  // redu[128+] and k_s0 visible to all
    const float inv_lo = redu[128 + rlo];
    const float inv_hi = redu[128 + rhi];

    for (int tile = 0; tile < 8; ++tile) {
        const int cur = tile & 1;
        const float* ksm = kbuf[cur];
        // issue async copies: V(tile) and K(tile+1)
        #pragma unroll
        for (int u = 0; u < 4; ++u) {
            int fi = t + u*256;
            int kr = fi >> 3, q4 = fi & 7;
            cp16(&v_sm[kr*40 + q4*4], vbase + (size_t)(tile*128 + kr)*256 + q4*4);
        }
        if (tile < 7) {
            float* dst = kbuf[cur ^ 1];
            #pragma unroll
            for (int u = 0; u < 4; ++u) {
                int fi = t + u*256;
                int kd = fi >> 5, c4 = fi & 31;
                cp16(&dst[kd*136 + c4*4], ktb + (size_t)kd*SS + (tile+1)*128 + c4*4);
            }
        }
        CP_COMMIT();
        // QK mma on current K tile (overlaps async copies)
        float acc[8][4];
        #pragma unroll
        for (int nt = 0; nt < 8; ++nt)
            #pragma unroll
            for (int j = 0; j < 4; ++j) acc[nt][j] = 0.f;
        #pragma unroll
        for (int ks = 0; ks < 4; ++ks) {
            float a0 = q_sm[rlo*36 + ks*8 + c];
            float a1 = q_sm[rhi*36 + ks*8 + c];
            float a2 = q_sm[rlo*36 + ks*8 + c + 4];
            float a3 = q_sm[rhi*36 + ks*8 + c + 4];
            #pragma unroll
            for (int nt = 0; nt < 8; ++nt) {
                int n0 = nh*64 + nt*8 + g;
                float b0 = ksm[(ks*8 + c)*136 + n0];
                float b1 = ksm[(ks*8 + c + 4)*136 + n0];
                mma_tf32(acc[nt], a0, a1, a2, a3, b0, b1);
            }
        }
        // w = exp(...)*inv*extra -> attn_w + w_tl   (still overlapping copies)
        #pragma unroll
        for (int nt = 0; nt < 8; ++nt) {
            int lkey = nh*64 + nt*8 + c*2;
            int key0 = tile*128 + lkey;
            float n0v = msk[key0], n1v = msk[key0+1];
            float2 elo = *(const float2*)(exlo + key0);
            float2 ehi = *(const float2*)(exhi + key0);
            float w0 = __expf(fmaf(acc[nt][0], scale, n0v)) * inv_lo * elo.x;
            float w1 = __expf(fmaf(acc[nt][1], scale, n1v)) * inv_lo * elo.y;
            float w2 = __expf(fmaf(acc[nt][2], scale, n0v)) * inv_hi * ehi.x;
            float w3 = __expf(fmaf(acc[nt][3], scale, n1v)) * inv_hi * ehi.y;
            if (wplo) {
                float2 o; o.x = w0; o.y = w1; *(float2*)(wplo + key0) = o;
                o.x = w2; o.y = w3; *(float2*)(wphi + key0) = o;
            }
            float2 s;
            s.x = to_tf32(w0); s.y = to_tf32(w1);
            *(float2*)(&w_tl[rlo*132 + lkey]) = s;
            s.x = to_tf32(w2); s.y = to_tf32(w3);
            *(float2*)(&w_tl[rhi*132 + lkey]) = s;
        }
        CP_WAIT0();
        __syncthreads();   // v_sm, w_tl, next K ready
        // PV mma
        #pragma unroll
        for (int ks = 0; ks < 8; ++ks) {
            int kb = nh*64 + ks*8;
            float a0 = w_tl[rlo*132 + kb + c];
            float a1 = w_tl[rhi*132 + kb + c];
            float a2 = w_tl[rlo*132 + kb + c + 4];
            float a3 = w_tl[rhi*132 + kb + c + 4];
            #pragma unroll
            for (int nt = 0; nt < 4; ++nt) {
                float b0 = v_sm[(kb + c)*40 + nt*8 + g];
                float b1 = v_sm[(kb + c + 4)*40 + nt*8 + g];
                mma_tf32(oc[nt], a0, a1, a2, a3, b0, b1);
            }
        }
        __syncthreads();   // PV done before v_sm/w_tl overwrite next tile
    }

    // ---- cross-half key reduction via smem ----
    #pragma unroll
    for (int nt = 0; nt < 4; ++nt) {
        float2 o;
        o.x = oc[nt][0]; o.y = oc[nt][1];
        *(float2*)(&w_tl[warp*544 + g*34 + nt*8 + c*2]) = o;
        o.x = oc[nt][2]; o.y = oc[nt][3];
        *(float2*)(&w_tl[warp*544 + (g+8)*34 + nt*8 + c*2]) = o;
    }
    __syncthreads();
    #pragma unroll
    for (int u = 0; u < 8; ++u) {
        int slot = t + u*256;
        int r = slot >> 5, d = slot & 31;
        int m4 = r >> 4, r16 = r & 15;
        float s = w_tl[m4*544 + r16*34 + d] + w_tl[(m4+4)*544 + r16*34 + d];
        Obuf[(size_t)(b*SS + q0 + r)*256 + coloff + d] = s;
    }
}

// ---------------- launch --------------------------------------------------
extern "C" void kernel_launch(void* const* d_in, const int* in_sizes, int n_in,
                              void* d_out, int out_size) {
    const float* v_ori = (const float*)d_in[0];
    const float* k_ori = (const float*)d_in[1];
    const float* q_ori = (const float*)d_in[2];
    const float* mask  = (const float*)d_in[3];
    const float* adj   = (const float*)d_in[4];
    const float* dist  = (const float*)d_in[5];
    const float* Wq_d = (const float*)d_in[6];  const float* bq_d = (const float*)d_in[7];
    const float* Wk_d = (const float*)d_in[8];  const float* bk_d = (const float*)d_in[9];
    const float* Wv_d = (const float*)d_in[10]; const float* bv_d = (const float*)d_in[11];
    const float* Wq_a = (const float*)d_in[12]; const float* bq_a = (const float*)d_in[13];
    const float* Wk_a = (const float*)d_in[14]; const float* bk_a = (const float*)d_in[15];
    const float* Wv_a = (const float*)d_in[16]; const float* bv_a = (const float*)d_in[17];
    const float* Wo   = (const float*)d_in[18]; const float* bo   = (const float*)d_in[19];

    float* out   = (float*)d_out;
    float* attnw = (out_size >= OUT_ELEMS + ATTN_ELEMS) ? out + OUT_ELEMS : (float*)0;

    float *pWq,*pWk,*pWv,*pbq,*pbk,*pbv,*pQ,*pK,*pV,*pKT,*pO,*pD;
    cudaGetSymbolAddress((void**)&pWq, g_Wq);
    cudaGetSymbolAddress((void**)&pWk, g_Wk);
    cudaGetSymbolAddress((void**)&pWv, g_Wv);
    cudaGetSymbolAddress((void**)&pbq, g_bq);
    cudaGetSymbolAddress((void**)&pbk, g_bk);
    cudaGetSymbolAddress((void**)&pbv, g_bv);
    cudaGetSymbolAddress((void**)&pQ,  g_Q);
    cudaGetSymbolAddress((void**)&pK,  g_K);
    cudaGetSymbolAddress((void**)&pV,  g_V);
    cudaGetSymbolAddress((void**)&pKT, g_KT);
    cudaGetSymbolAddress((void**)&pO,  g_O);
    cudaGetSymbolAddress((void**)&pD,  g_Dsm);

    const int ATTN_SMEM = 25792 * 4;   // 103,168 B -> 2 CTAs/SM
    cudaFuncSetAttribute(attn_kernel, cudaFuncAttributeMaxDynamicSharedMemorySize, ATTN_SMEM);

    // #0: fused pack
    pack3_kernel<<<dim3(256, 3), 256>>>(Wq_d, Wq_a, bq_d, bq_a,
                                        Wk_d, Wk_a, bk_d, bk_a,
                                        Wv_d, Wv_a, bv_d, bv_a,
                                        pWq, pbq, pWk, pbk, pWv, pbv);
    // #1-3: projections
    dim3 ggrid(128, 2);
    gemm2_kernel<<<ggrid, 256>>>(q_ori, pWq, pbq, pQ);
    gemm2_kernel<<<ggrid, 256>>>(k_ori, pWk, pbk, pK);
    gemm2_kernel<<<ggrid, 256>>>(v_ori, pWv, pbv, pV);

    // #4: fused dist-softmax + K-transpose(tf32) + V tf32-round
    prep_kernel<<<16384 + 4096 + 4096, 256>>>(dist, mask, pK, pD, pKT, pV);

    // #5: fused attention (two-pass streaming, cp.async pipelined, tf32 mma)
    dim3 agrid(16, 8, 16);
    attn_kernel<<<agrid, 256, ATTN_SMEM>>>(pQ, pKT, pV, mask, pD, adj, attnw, pO);

    // #6: output projection
    gemm2_kernel<<<ggrid, 256>>>(pO, Wo, bo, out);
}